// round 8
// baseline (speedup 1.0000x reference)
#include <cuda_runtime.h>
#include <cstdint>

#define NPIX (512*512)

typedef unsigned long long u64;

// Scratch (device) -> CMEM (constant) staging. Layout (float indices):
// [0,8192)     A[b][i][j] = zf[b][i] * W1[i][j]   (8 x 32 x 32, j contiguous)
// [8192,9216)  W2T pairs:  [j][ip] = (W2[2ip][j], W2[2ip+1][j])  (32 x 16 x 2)
// [9216,9248)  b1
// [9248,9312)  (b2[j], W3[j]) interleaved pairs
// [9312]       b3
#define N_CONST 9313
__device__ float gScratch[N_CONST];
__constant__ float CMEM[N_CONST];

#define OFF_A    0u
#define OFF_W2T  32768u
#define OFF_B1   36864u
#define OFF_BW   36992u
#define OFF_B3   37248u

// Packed fp32x2 FMA (Blackwell-only; not emitted by ptxas from C++).
__device__ __forceinline__ u64 ffma2(u64 a, u64 b, u64 c) {
    u64 d;
    asm("fma.rn.f32x2 %0, %1, %2, %3;" : "=l"(d) : "l"(a), "l"(b), "l"(c));
    return d;
}
__device__ __forceinline__ u64 dup2(float f) {
    u64 d;
    unsigned r = __float_as_uint(f);
    asm("mov.b64 %0, {%1, %1};" : "=l"(d) : "r"(r));
    return d;
}
__device__ __forceinline__ u64 pack2(float lo, float hi) {
    u64 d;
    asm("mov.b64 %0, {%1, %2};" : "=l"(d) : "r"(__float_as_uint(lo)), "r"(__float_as_uint(hi)));
    return d;
}
__device__ __forceinline__ float2 unpack2(u64 v) {
    float2 r;
    unsigned lo, hi;
    asm("mov.b64 {%0, %1}, %2;" : "=r"(lo), "=r"(hi) : "l"(v));
    r.x = __uint_as_float(lo); r.y = __uint_as_float(hi);
    return r;
}

// Volatile constant loads: uniform address -> LDCU (uniform regs, 16B/warp,
// own port). Volatile = anti-hoist (the register-promotion spill protection
// that every passing round has relied on).
__device__ __forceinline__ ulonglong2 ldc128(uint64_t caddr) {
    ulonglong2 v;
    asm volatile("ld.const.v2.u64 {%0, %1}, [%2];" : "=l"(v.x), "=l"(v.y) : "l"(caddr));
    return v;
}
__device__ __forceinline__ u64 ldc64(uint64_t caddr) {
    u64 v;
    asm volatile("ld.const.u64 %0, [%1];" : "=l"(v) : "l"(caddr));
    return v;
}
__device__ __forceinline__ float ldc32(uint64_t caddr) {
    float v;
    asm volatile("ld.const.f32 %0, [%1];" : "=f"(v) : "l"(caddr));
    return v;
}

// Prologue: fold z-features into layer-1 weights (both grid-constant) and
// pre-transpose W2; stage everything for the constant bank.
__global__ void prep_kernel(const float* __restrict__ z,
                            const float* __restrict__ z_data,
                            const float* __restrict__ W1,
                            const float* __restrict__ W2,
                            const float* __restrict__ b1,
                            const float* __restrict__ b2,
                            const float* __restrict__ W3,
                            const float* __restrict__ b3) {
    const int idx = blockIdx.x * 256 + threadIdx.x;
    if (idx >= N_CONST) return;
    float v;
    if (idx < 8192) {
        const int b = idx >> 10, r = idx & 1023, i = r >> 5, j = r & 31;
        const float zn = 63.0f * z[b];
        int z0i = (int)zn;
        if (z0i < 0) z0i = 0;
        if (z0i > 63) z0i = 63;
        int z1i = z0i + 1;
        if (z1i > 63) z1i = 63;
        const float zl = zn - truncf(zn);
        const float zf = z_data[z0i * 32 + i] * (1.0f - zl) + z_data[z1i * 32 + i] * zl;
        v = zf * W1[i * 32 + j];
    } else if (idx < 9216) {
        const int t = idx - 8192, j = t >> 5, r = t & 31, ip = r >> 1, hf = r & 1;
        v = W2[(2 * ip + hf) * 32 + j];
    } else if (idx < 9248) {
        v = b1[idx - 9216];
    } else if (idx < 9312) {
        const int t = idx - 9248;
        v = (t & 1) ? W3[t >> 1] : b2[t >> 1];
    } else {
        v = b3[0];
    }
    gScratch[idx] = v;
}

__global__ __launch_bounds__(128, 4) void g_tensor3d_kernel(
    const float* __restrict__ data,     // [512,512,32]
    const float* __restrict__ lerp,     // [NPIX,2]
    const int*   __restrict__ x0,
    const int*   __restrict__ y0,
    const int*   __restrict__ x1,
    const int*   __restrict__ y1,
    float*       __restrict__ out)      // [8, NPIX]
{
    uint64_t aC;
    asm("cvta.to.const.u64 %0, %1;" : "=l"(aC) : "l"(CMEM));

    const int p = blockIdx.x * 128 + threadIdx.x;

    const float2 lw = ((const float2*)lerp)[p];
    const float wx = lw.x, wy = lw.y;
    const int ix0 = x0[p], iy0 = y0[p], ix1 = x1[p], iy1 = y1[p];

    const float4* p00 = (const float4*)(data + (iy0 * 512 + ix0) * 32);
    const float4* p10 = (const float4*)(data + (iy0 * 512 + ix1) * 32);
    const float4* p01 = (const float4*)(data + (iy1 * 512 + ix0) * 32);
    const float4* p11 = (const float4*)(data + (iy1 * 512 + ix1) * 32);

    const float w00 = (1.0f - wx) * (1.0f - wy);
    const float w10 = wx * (1.0f - wy);
    const float w01 = (1.0f - wx) * wy;
    const float w11 = wx * wy;

    // Bilinear gather -> registers (no smem anywhere in this kernel).
    float xy[32];
    #pragma unroll
    for (int q = 0; q < 8; q++) {
        const float4 a = p00[q];
        const float4 c = p10[q];
        const float4 e = p01[q];
        const float4 g = p11[q];
        xy[4 * q + 0] = a.x * w00 + c.x * w10 + e.x * w01 + g.x * w11;
        xy[4 * q + 1] = a.y * w00 + c.y * w10 + e.y * w01 + g.y * w11;
        xy[4 * q + 2] = a.z * w00 + c.z * w10 + e.z * w01 + g.z * w11;
        xy[4 * q + 3] = a.w * w00 + c.w * w10 + e.w * w01 + g.w * w11;
    }

    const float b3v = ldc32(aC + OFF_B3);

    // 4 passes x 2 batches. zf is folded into the per-batch layer-1 weights,
    // so the L1 activation is just dup2(xy[i]), shared by both batches.
    #pragma unroll 1
    for (int pass = 0; pass < 4; pass++) {
        const uint64_t aA0 = aC + OFF_A + (uint64_t)(2 * pass) * 4096u;
        const uint64_t aA1 = aA0 + 4096u;

        // ---- Layer 1: h1[b][jp] = xy @ A_b + b1, packed over j ----
        u64 h1[32];
        #pragma unroll
        for (int jp = 0; jp < 16; jp++) {
            const u64 bb = ldc64(aC + OFF_B1 + jp * 8);
            h1[jp]      = bb;
            h1[16 + jp] = bb;
        }

        #pragma unroll
        for (int i = 0; i < 32; i++) {
            const u64 fd = dup2(xy[i]);
            #pragma unroll
            for (int q = 0; q < 8; q++) {
                const ulonglong2 w = ldc128(aA0 + i * 128 + q * 16);
                h1[2 * q + 0] = ffma2(fd, w.x, h1[2 * q + 0]);
                h1[2 * q + 1] = ffma2(fd, w.y, h1[2 * q + 1]);
            }
            #pragma unroll
            for (int q = 0; q < 8; q++) {
                const ulonglong2 w = ldc128(aA1 + i * 128 + q * 16);
                h1[16 + 2 * q + 0] = ffma2(fd, w.x, h1[16 + 2 * q + 0]);
                h1[16 + 2 * q + 1] = ffma2(fd, w.y, h1[16 + 2 * q + 1]);
            }
        }

        // ReLU in place (pairs stay packed over layer-2's i dimension).
        #pragma unroll
        for (int m = 0; m < 32; m++) {
            const float2 v = unpack2(h1[m]);
            h1[m] = pack2(fmaxf(v.x, 0.0f), fmaxf(v.y, 0.0f));
        }

        // ---- Layer 2 + 3 streamed per output j (i-packed W2T) ----
        float o0 = 0.0f, o1 = 0.0f;
        #pragma unroll 2
        for (int j = 0; j < 32; j++) {
            u64 a0 = 0ull, a1 = 0ull;
            const uint64_t wb = aC + OFF_W2T + (uint64_t)j * 128u;
            #pragma unroll
            for (int q = 0; q < 8; q++) {
                const ulonglong2 w = ldc128(wb + q * 16);
                a0 = ffma2(h1[2 * q + 0], w.x, a0);
                a0 = ffma2(h1[2 * q + 1], w.y, a0);
                a1 = ffma2(h1[16 + 2 * q + 0], w.x, a1);
                a1 = ffma2(h1[16 + 2 * q + 1], w.y, a1);
            }
            const float2 bw = unpack2(ldc64(aC + OFF_BW + j * 8));  // (b2[j], W3[j])
            const float2 t0 = unpack2(a0);
            const float2 t1 = unpack2(a1);
            o0 = fmaf(fmaxf(t0.x + t0.y + bw.x, 0.0f), bw.y, o0);
            o1 = fmaf(fmaxf(t1.x + t1.y + bw.x, 0.0f), bw.y, o1);
        }

        out[(2 * pass + 0) * NPIX + p] = o0 + b3v;
        out[(2 * pass + 1) * NPIX + p] = o1 + b3v;
    }
}

extern "C" void kernel_launch(void* const* d_in, const int* in_sizes, int n_in,
                              void* d_out, int out_size) {
    const float* z      = (const float*)d_in[0];
    const float* data   = (const float*)d_in[1];
    const float* z_data = (const float*)d_in[2];
    const float* lerp   = (const float*)d_in[3];
    const int*   x0     = (const int*)d_in[4];
    const int*   y0     = (const int*)d_in[5];
    const int*   x1     = (const int*)d_in[6];
    const int*   y1     = (const int*)d_in[7];
    const float* W1     = (const float*)d_in[8];
    const float* b1     = (const float*)d_in[9];
    const float* W2     = (const float*)d_in[10];
    const float* b2     = (const float*)d_in[11];
    const float* W3     = (const float*)d_in[12];
    const float* b3     = (const float*)d_in[13];
    float* out = (float*)d_out;

    // Stage folded weights into constant memory (all default-stream,
    // graph-capturable: kernel + D2D memcpy node).
    prep_kernel<<<(N_CONST + 255) / 256, 256>>>(z, z_data, W1, W2, b1, b2, W3, b3);
    void* src = nullptr;
    cudaGetSymbolAddress(&src, gScratch);
    cudaMemcpyToSymbolAsync(CMEM, src, N_CONST * sizeof(float), 0,
                            cudaMemcpyDeviceToDevice, 0);

    g_tensor3d_kernel<<<NPIX / 128, 128>>>(data, lerp, x0, y0, x1, y1, out);
}

// round 9
// speedup vs baseline: 1.8323x; 1.8323x over previous
#include <cuda_runtime.h>
#include <cstdint>

#define NPIX (512*512)

typedef unsigned long long u64;

// Packed fp32x2 FMA (Blackwell-only; not emitted by ptxas from C++).
__device__ __forceinline__ u64 ffma2(u64 a, u64 b, u64 c) {
    u64 d;
    asm("fma.rn.f32x2 %0, %1, %2, %3;" : "=l"(d) : "l"(a), "l"(b), "l"(c));
    return d;
}
__device__ __forceinline__ u64 dup2(float f) {
    u64 d;
    unsigned r = __float_as_uint(f);
    asm("mov.b64 %0, {%1, %1};" : "=l"(d) : "r"(r));
    return d;
}
__device__ __forceinline__ u64 pack2(float lo, float hi) {
    u64 d;
    asm("mov.b64 %0, {%1, %2};" : "=l"(d) : "r"(__float_as_uint(lo)), "r"(__float_as_uint(hi)));
    return d;
}
__device__ __forceinline__ float2 unpack2(u64 v) {
    float2 r;
    unsigned lo, hi;
    asm("mov.b64 {%0, %1}, %2;" : "=r"(lo), "=r"(hi) : "l"(v));
    r.x = __uint_as_float(lo); r.y = __uint_as_float(hi);
    return r;
}

// Anti-hoist shared accesses (volatile asm: no CSE / no motion across the
// pass loop -> prevents the giant weight->register promotion spills).
__device__ __forceinline__ uint32_t sptr(const void* p) {
    return (uint32_t)__cvta_generic_to_shared(p);
}
__device__ __forceinline__ ulonglong2 lds128v(uint32_t addr) {
    ulonglong2 v;
    asm volatile("ld.shared.v2.u64 {%0, %1}, [%2];" : "=l"(v.x), "=l"(v.y) : "r"(addr));
    return v;
}
__device__ __forceinline__ u64 lds64v(uint32_t addr) {
    u64 v;
    asm volatile("ld.shared.u64 %0, [%1];" : "=l"(v) : "r"(addr));
    return v;
}
__device__ __forceinline__ float2 ldsf2v(uint32_t addr) {
    float2 v;
    asm volatile("ld.shared.v2.f32 {%0, %1}, [%2];" : "=f"(v.x), "=f"(v.y) : "r"(addr));
    return v;
}
__device__ __forceinline__ float ldsf1v(uint32_t addr) {
    float v;
    asm volatile("ld.shared.f32 %0, [%1];" : "=f"(v) : "r"(addr));
    return v;
}
__device__ __forceinline__ void stsf1v(uint32_t addr, float v) {
    asm volatile("st.shared.f32 [%0], %1;" :: "r"(addr), "f"(v));
}

__global__ __launch_bounds__(128, 4) void g_tensor3d_kernel(
    const float* __restrict__ z,        // [8]
    const float* __restrict__ data,     // [512,512,32]
    const float* __restrict__ z_data,   // [64,32]
    const float* __restrict__ lerp,     // [NPIX,2]
    const int*   __restrict__ x0,
    const int*   __restrict__ y0,
    const int*   __restrict__ x1,
    const int*   __restrict__ y1,
    const float* __restrict__ W1,       // [32,32]
    const float* __restrict__ b1,
    const float* __restrict__ W2,       // [32,32]
    const float* __restrict__ b2,
    const float* __restrict__ W3,       // [32]
    const float* __restrict__ b3,
    float*       __restrict__ out)      // [8, NPIX]
{
    __shared__ ulonglong2 sW1p[256];    // L1 weights, j-packed: row i = 8 ulonglong2
    __shared__ u64 sW2T[512];           // L2 weights, i-packed: [j][ip] = (W2[2ip][j], W2[2ip+1][j])
    __shared__ u64 sb1p[16];
    __shared__ float2 sb2w3[32];        // (b2[j], W3[j])
    __shared__ float szfT[256];         // transposed z-features: [i][b]
    __shared__ float sxy[128 * 33];     // per-thread pixel feature, stride 33
    __shared__ float sb3v;

    const int tid = threadIdx.x;

    #pragma unroll
    for (int k = 0; k < 2; k++)
        sW1p[tid + 128 * k] = ((const ulonglong2*)W1)[tid + 128 * k];

    // W2 transposed + i-packed.
    #pragma unroll
    for (int k = 0; k < 4; k++) {
        const int idx = tid + 128 * k;     // 0..511
        const int j  = idx >> 4;
        const int ip = idx & 15;
        sW2T[j * 16 + ip] = pack2(W2[(2 * ip) * 32 + j], W2[(2 * ip + 1) * 32 + j]);
    }
    if (tid < 16) sb1p[tid] = ((const u64*)b1)[tid];
    if (tid < 32) { float2 t; t.x = b2[tid]; t.y = W3[tid]; sb2w3[tid] = t; }
    if (tid == 0) sb3v = b3[0];

    // z features, transposed: [i][b].
    #pragma unroll
    for (int k = 0; k < 2; k++) {
        const int t = tid + 128 * k;
        const int b = t >> 5;
        const int i = t & 31;
        const float zn = 63.0f * z[b];
        const float zt = truncf(zn);
        int z0i = (int)zn;
        if (z0i < 0) z0i = 0;
        if (z0i > 63) z0i = 63;
        int z1i = z0i + 1;
        if (z1i > 63) z1i = 63;
        const float zl = zn - zt;
        szfT[i * 8 + b] = z_data[z0i * 32 + i] * (1.0f - zl) + z_data[z1i * 32 + i] * zl;
    }
    __syncthreads();

    const uint32_t w1base  = sptr(sW1p);
    const uint32_t w2tbase = sptr(sW2T);
    const uint32_t b1base  = sptr(sb1p);
    const uint32_t bw2base = sptr(sb2w3);
    const uint32_t zfbase  = sptr(szfT);
    const uint32_t xybase  = sptr(sxy) + tid * 33 * 4;

    const int p = blockIdx.x * 128 + tid;

    const float wx = lerp[2 * p + 0];
    const float wy = lerp[2 * p + 1];
    const int ix0 = x0[p], iy0 = y0[p], ix1 = x1[p], iy1 = y1[p];

    const float4* p00 = (const float4*)(data + (iy0 * 512 + ix0) * 32);
    const float4* p10 = (const float4*)(data + (iy0 * 512 + ix1) * 32);
    const float4* p01 = (const float4*)(data + (iy1 * 512 + ix0) * 32);
    const float4* p11 = (const float4*)(data + (iy1 * 512 + ix1) * 32);

    const float w00 = (1.0f - wx) * (1.0f - wy);
    const float w10 = wx * (1.0f - wy);
    const float w01 = (1.0f - wx) * wy;
    const float w11 = wx * wy;

    // Bilinear gather -> per-thread shared lane (keeps registers low).
    #pragma unroll
    for (int q = 0; q < 8; q++) {
        const float4 a = p00[q];
        const float4 c = p10[q];
        const float4 e = p01[q];
        const float4 g = p11[q];
        stsf1v(xybase + (4 * q + 0) * 4, a.x * w00 + c.x * w10 + e.x * w01 + g.x * w11);
        stsf1v(xybase + (4 * q + 1) * 4, a.y * w00 + c.y * w10 + e.y * w01 + g.y * w11);
        stsf1v(xybase + (4 * q + 2) * 4, a.z * w00 + c.z * w10 + e.z * w01 + g.z * w11);
        stsf1v(xybase + (4 * q + 3) * 4, a.w * w00 + c.w * w10 + e.w * w01 + g.w * w11);
    }

    const float bias3 = sb3v;

    // 2 batches per pass x 4 passes: h1 = 32 u64 = 64 regs -> 4 CTAs/SM.
    #pragma unroll 1
    for (int pass = 0; pass < 4; pass++) {
        // ---- Layer 1: h1[k][jp] packed over j ----
        u64 h1[32];
        #pragma unroll
        for (int jp = 0; jp < 16; jp++) {
            const u64 bb = lds64v(b1base + 8 * jp);
            h1[jp]      = bb;
            h1[16 + jp] = bb;
        }

        #pragma unroll
        for (int i = 0; i < 32; i++) {
            const float2 zf = ldsf2v(zfbase + i * 32 + pass * 8);
            const float xv = ldsf1v(xybase + i * 4);
            const u64 f0 = dup2(xv * zf.x);
            const u64 f1 = dup2(xv * zf.y);
            #pragma unroll
            for (int q = 0; q < 8; q++) {
                const ulonglong2 wv = lds128v(w1base + (i * 8 + q) * 16);
                h1[2 * q + 0]      = ffma2(f0, wv.x, h1[2 * q + 0]);
                h1[2 * q + 1]      = ffma2(f0, wv.y, h1[2 * q + 1]);
                h1[16 + 2 * q + 0] = ffma2(f1, wv.x, h1[16 + 2 * q + 0]);
                h1[16 + 2 * q + 1] = ffma2(f1, wv.y, h1[16 + 2 * q + 1]);
            }
        }

        // ReLU in place (pairs stay packed over layer-2's i dimension).
        #pragma unroll
        for (int m = 0; m < 32; m++) {
            const float2 v = unpack2(h1[m]);
            h1[m] = pack2(fmaxf(v.x, 0.0f), fmaxf(v.y, 0.0f));
        }

        // ---- Layer 2 + 3 streamed per output j (i-packed W2T) ----
        float o0 = 0.0f, o1 = 0.0f;

        #pragma unroll 2
        for (int j = 0; j < 32; j++) {
            u64 a0 = 0ull, a1 = 0ull;
            const uint32_t wb = w2tbase + j * 128;
            #pragma unroll
            for (int q = 0; q < 8; q++) {
                const ulonglong2 wv = lds128v(wb + q * 16);
                a0 = ffma2(h1[2 * q + 0], wv.x, a0);
                a1 = ffma2(h1[16 + 2 * q + 0], wv.x, a1);
                a0 = ffma2(h1[2 * q + 1], wv.y, a0);
                a1 = ffma2(h1[16 + 2 * q + 1], wv.y, a1);
            }
            const float2 bw = ldsf2v(bw2base + j * 8);   // (b2[j], W3[j])
            const float2 t0 = unpack2(a0);
            const float2 t1 = unpack2(a1);
            o0 = fmaf(fmaxf(t0.x + t0.y + bw.x, 0.0f), bw.y, o0);
            o1 = fmaf(fmaxf(t1.x + t1.y + bw.x, 0.0f), bw.y, o1);
        }

        out[(2 * pass + 0) * NPIX + p] = o0 + bias3;
        out[(2 * pass + 1) * NPIX + p] = o1 + bias3;
    }
}

extern "C" void kernel_launch(void* const* d_in, const int* in_sizes, int n_in,
                              void* d_out, int out_size) {
    const float* z      = (const float*)d_in[0];
    const float* data   = (const float*)d_in[1];
    const float* z_data = (const float*)d_in[2];
    const float* lerp   = (const float*)d_in[3];
    const int*   x0     = (const int*)d_in[4];
    const int*   y0     = (const int*)d_in[5];
    const int*   x1     = (const int*)d_in[6];
    const int*   y1     = (const int*)d_in[7];
    const float* W1     = (const float*)d_in[8];
    const float* b1     = (const float*)d_in[9];
    const float* W2     = (const float*)d_in[10];
    const float* b2     = (const float*)d_in[11];
    const float* W3     = (const float*)d_in[12];
    const float* b3     = (const float*)d_in[13];
    float* out = (float*)d_out;

    g_tensor3d_kernel<<<NPIX / 128, 128>>>(z, data, z_data, lerp,
                                           x0, y0, x1, y1,
                                           W1, b1, W2, b2, W3, b3, out);
}

// round 10
// speedup vs baseline: 2.1060x; 1.1494x over previous
#include <cuda_runtime.h>
#include <cstdint>

#define NPIX (512*512)

typedef unsigned long long u64;

// Packed fp32x2 FMA (Blackwell-only; not emitted by ptxas from C++).
__device__ __forceinline__ u64 ffma2(u64 a, u64 b, u64 c) {
    u64 d;
    asm("fma.rn.f32x2 %0, %1, %2, %3;" : "=l"(d) : "l"(a), "l"(b), "l"(c));
    return d;
}
__device__ __forceinline__ u64 dup2(float f) {
    u64 d;
    unsigned r = __float_as_uint(f);
    asm("mov.b64 %0, {%1, %1};" : "=l"(d) : "r"(r));
    return d;
}
__device__ __forceinline__ u64 pack2(float lo, float hi) {
    u64 d;
    asm("mov.b64 %0, {%1, %2};" : "=l"(d) : "r"(__float_as_uint(lo)), "r"(__float_as_uint(hi)));
    return d;
}
__device__ __forceinline__ float2 unpack2(u64 v) {
    float2 r;
    unsigned lo, hi;
    asm("mov.b64 {%0, %1}, %2;" : "=r"(lo), "=r"(hi) : "l"(v));
    r.x = __uint_as_float(lo); r.y = __uint_as_float(hi);
    return r;
}

// Anti-hoist shared accesses (volatile asm: no CSE / no motion across the
// pass loop -> prevents the giant weight->register promotion spills).
__device__ __forceinline__ uint32_t sptr(const void* p) {
    return (uint32_t)__cvta_generic_to_shared(p);
}
__device__ __forceinline__ ulonglong2 lds128v(uint32_t addr) {
    ulonglong2 v;
    asm volatile("ld.shared.v2.u64 {%0, %1}, [%2];" : "=l"(v.x), "=l"(v.y) : "r"(addr));
    return v;
}
__device__ __forceinline__ u64 lds64v(uint32_t addr) {
    u64 v;
    asm volatile("ld.shared.u64 %0, [%1];" : "=l"(v) : "r"(addr));
    return v;
}
__device__ __forceinline__ float4 ldsf4v(uint32_t addr) {
    float4 v;
    asm volatile("ld.shared.v4.f32 {%0, %1, %2, %3}, [%4];"
                 : "=f"(v.x), "=f"(v.y), "=f"(v.z), "=f"(v.w) : "r"(addr));
    return v;
}
__device__ __forceinline__ float2 ldsf2v(uint32_t addr) {
    float2 v;
    asm volatile("ld.shared.v2.f32 {%0, %1}, [%2];" : "=f"(v.x), "=f"(v.y) : "r"(addr));
    return v;
}
__device__ __forceinline__ float ldsf1v(uint32_t addr) {
    float v;
    asm volatile("ld.shared.f32 %0, [%1];" : "=f"(v) : "r"(addr));
    return v;
}
__device__ __forceinline__ void stsf1v(uint32_t addr, float v) {
    asm volatile("st.shared.f32 [%0], %1;" :: "r"(addr), "f"(v));
}

__global__ __launch_bounds__(128, 2) void g_tensor3d_kernel(
    const float* __restrict__ z,        // [8]
    const float* __restrict__ data,     // [512,512,32]
    const float* __restrict__ z_data,   // [64,32]
    const float* __restrict__ lerp,     // [NPIX,2]
    const int*   __restrict__ x0,
    const int*   __restrict__ y0,
    const int*   __restrict__ x1,
    const int*   __restrict__ y1,
    const float* __restrict__ W1,       // [32,32]
    const float* __restrict__ b1,
    const float* __restrict__ W2,       // [32,32]
    const float* __restrict__ b2,
    const float* __restrict__ W3,       // [32]
    const float* __restrict__ b3,
    float*       __restrict__ out)      // [8, NPIX]
{
    __shared__ ulonglong2 sW1p[256];    // L1 weights, j-packed: row i = 8 ulonglong2
    __shared__ u64 sW2T[512];           // L2 weights, i-packed: [j][ip] = (W2[2ip][j], W2[2ip+1][j])
    __shared__ u64 sb1p[16];
    __shared__ float2 sb2w3[32];        // (b2[j], W3[j])
    __shared__ float szfT[256];         // transposed z-features: [i][b]
    __shared__ float sxy[128 * 33];     // per-thread pixel feature, stride 33
    __shared__ float sb3v;

    const int tid = threadIdx.x;

    #pragma unroll
    for (int k = 0; k < 2; k++)
        sW1p[tid + 128 * k] = ((const ulonglong2*)W1)[tid + 128 * k];

    // W2 transposed + i-packed.
    #pragma unroll
    for (int k = 0; k < 4; k++) {
        const int idx = tid + 128 * k;     // 0..511
        const int j  = idx >> 4;
        const int ip = idx & 15;
        sW2T[j * 16 + ip] = pack2(W2[(2 * ip) * 32 + j], W2[(2 * ip + 1) * 32 + j]);
    }
    if (tid < 16) sb1p[tid] = ((const u64*)b1)[tid];
    if (tid < 32) { float2 t; t.x = b2[tid]; t.y = W3[tid]; sb2w3[tid] = t; }
    if (tid == 0) sb3v = b3[0];

    // z features, transposed: [i][b].
    #pragma unroll
    for (int k = 0; k < 2; k++) {
        const int t = tid + 128 * k;
        const int b = t >> 5;
        const int i = t & 31;
        const float zn = 63.0f * z[b];
        const float zt = truncf(zn);
        int z0i = (int)zn;
        if (z0i < 0) z0i = 0;
        if (z0i > 63) z0i = 63;
        int z1i = z0i + 1;
        if (z1i > 63) z1i = 63;
        const float zl = zn - zt;
        szfT[i * 8 + b] = z_data[z0i * 32 + i] * (1.0f - zl) + z_data[z1i * 32 + i] * zl;
    }
    __syncthreads();

    const uint32_t w1base  = sptr(sW1p);
    const uint32_t w2tbase = sptr(sW2T);
    const uint32_t b1base  = sptr(sb1p);
    const uint32_t bw2base = sptr(sb2w3);
    const uint32_t zfbase  = sptr(szfT);
    const uint32_t xybase  = sptr(sxy) + tid * 33 * 4;

    const int p = blockIdx.x * 128 + tid;

    const float wx = lerp[2 * p + 0];
    const float wy = lerp[2 * p + 1];
    const int ix0 = x0[p], iy0 = y0[p], ix1 = x1[p], iy1 = y1[p];

    const float4* p00 = (const float4*)(data + (iy0 * 512 + ix0) * 32);
    const float4* p10 = (const float4*)(data + (iy0 * 512 + ix1) * 32);
    const float4* p01 = (const float4*)(data + (iy1 * 512 + ix0) * 32);
    const float4* p11 = (const float4*)(data + (iy1 * 512 + ix1) * 32);

    const float w00 = (1.0f - wx) * (1.0f - wy);
    const float w10 = wx * (1.0f - wy);
    const float w01 = (1.0f - wx) * wy;
    const float w11 = wx * wy;

    // Bilinear gather -> per-thread shared lane (keeps registers low).
    #pragma unroll
    for (int q = 0; q < 8; q++) {
        const float4 a = p00[q];
        const float4 c = p10[q];
        const float4 e = p01[q];
        const float4 g = p11[q];
        stsf1v(xybase + (4 * q + 0) * 4, a.x * w00 + c.x * w10 + e.x * w01 + g.x * w11);
        stsf1v(xybase + (4 * q + 1) * 4, a.y * w00 + c.y * w10 + e.y * w01 + g.y * w11);
        stsf1v(xybase + (4 * q + 2) * 4, a.z * w00 + c.z * w10 + e.z * w01 + g.z * w11);
        stsf1v(xybase + (4 * q + 3) * 4, a.w * w00 + c.w * w10 + e.w * w01 + g.w * w11);
    }

    const float bias3 = sb3v;

    // 4 batches per pass; weight loads burst 8-wide (MLP=8) before any
    // consuming FMA so one LDS latency is covered by 64 FFMA2 of work.
    #pragma unroll 1
    for (int pass = 0; pass < 2; pass++) {
        // ---- Layer 1: h1[k][jp] packed over j ----
        u64 h1[64];
        #pragma unroll
        for (int jp = 0; jp < 16; jp++) {
            const u64 bb = lds64v(b1base + 8 * jp);
            h1[0 * 16 + jp] = bb;
            h1[1 * 16 + jp] = bb;
            h1[2 * 16 + jp] = bb;
            h1[3 * 16 + jp] = bb;
        }

        #pragma unroll
        for (int i = 0; i < 32; i++) {
            // Burst: all 8 weight pairs + activations in flight together.
            ulonglong2 wv[8];
            #pragma unroll
            for (int q = 0; q < 8; q++)
                wv[q] = lds128v(w1base + (i * 8 + q) * 16);
            const float4 zf = ldsf4v(zfbase + i * 32 + pass * 16);
            const float xv = ldsf1v(xybase + i * 4);
            const u64 f0 = dup2(xv * zf.x);
            const u64 f1 = dup2(xv * zf.y);
            const u64 f2 = dup2(xv * zf.z);
            const u64 f3 = dup2(xv * zf.w);
            #pragma unroll
            for (int q = 0; q < 8; q++) {
                h1[0 * 16 + 2 * q + 0] = ffma2(f0, wv[q].x, h1[0 * 16 + 2 * q + 0]);
                h1[0 * 16 + 2 * q + 1] = ffma2(f0, wv[q].y, h1[0 * 16 + 2 * q + 1]);
                h1[1 * 16 + 2 * q + 0] = ffma2(f1, wv[q].x, h1[1 * 16 + 2 * q + 0]);
                h1[1 * 16 + 2 * q + 1] = ffma2(f1, wv[q].y, h1[1 * 16 + 2 * q + 1]);
                h1[2 * 16 + 2 * q + 0] = ffma2(f2, wv[q].x, h1[2 * 16 + 2 * q + 0]);
                h1[2 * 16 + 2 * q + 1] = ffma2(f2, wv[q].y, h1[2 * 16 + 2 * q + 1]);
                h1[3 * 16 + 2 * q + 0] = ffma2(f3, wv[q].x, h1[3 * 16 + 2 * q + 0]);
                h1[3 * 16 + 2 * q + 1] = ffma2(f3, wv[q].y, h1[3 * 16 + 2 * q + 1]);
            }
        }

        // ReLU in place (pairs stay packed over layer-2's i dimension).
        #pragma unroll
        for (int m = 0; m < 64; m++) {
            const float2 v = unpack2(h1[m]);
            h1[m] = pack2(fmaxf(v.x, 0.0f), fmaxf(v.y, 0.0f));
        }

        // ---- Layer 2 + 3 streamed per output j (i-packed W2T) ----
        float o0 = 0.0f, o1 = 0.0f, o2 = 0.0f, o3 = 0.0f;

        #pragma unroll 2
        for (int j = 0; j < 32; j++) {
            ulonglong2 wv[8];
            const uint32_t wb = w2tbase + j * 128;
            #pragma unroll
            for (int q = 0; q < 8; q++)
                wv[q] = lds128v(wb + q * 16);

            u64 a0 = 0ull, a1 = 0ull, a2 = 0ull, a3 = 0ull;
            #pragma unroll
            for (int q = 0; q < 8; q++) {
                a0 = ffma2(h1[0 * 16 + 2 * q + 0], wv[q].x, a0);
                a1 = ffma2(h1[1 * 16 + 2 * q + 0], wv[q].x, a1);
                a2 = ffma2(h1[2 * 16 + 2 * q + 0], wv[q].x, a2);
                a3 = ffma2(h1[3 * 16 + 2 * q + 0], wv[q].x, a3);
                a0 = ffma2(h1[0 * 16 + 2 * q + 1], wv[q].y, a0);
                a1 = ffma2(h1[1 * 16 + 2 * q + 1], wv[q].y, a1);
                a2 = ffma2(h1[2 * 16 + 2 * q + 1], wv[q].y, a2);
                a3 = ffma2(h1[3 * 16 + 2 * q + 1], wv[q].y, a3);
            }
            const float2 bw = ldsf2v(bw2base + j * 8);   // (b2[j], W3[j])
            const float2 t0 = unpack2(a0);
            const float2 t1 = unpack2(a1);
            const float2 t2 = unpack2(a2);
            const float2 t3 = unpack2(a3);
            o0 = fmaf(fmaxf(t0.x + t0.y + bw.x, 0.0f), bw.y, o0);
            o1 = fmaf(fmaxf(t1.x + t1.y + bw.x, 0.0f), bw.y, o1);
            o2 = fmaf(fmaxf(t2.x + t2.y + bw.x, 0.0f), bw.y, o2);
            o3 = fmaf(fmaxf(t3.x + t3.y + bw.x, 0.0f), bw.y, o3);
        }

        out[(4 * pass + 0) * NPIX + p] = o0 + bias3;
        out[(4 * pass + 1) * NPIX + p] = o1 + bias3;
        out[(4 * pass + 2) * NPIX + p] = o2 + bias3;
        out[(4 * pass + 3) * NPIX + p] = o3 + bias3;
    }
}

extern "C" void kernel_launch(void* const* d_in, const int* in_sizes, int n_in,
                              void* d_out, int out_size) {
    const float* z      = (const float*)d_in[0];
    const float* data   = (const float*)d_in[1];
    const float* z_data = (const float*)d_in[2];
    const float* lerp   = (const float*)d_in[3];
    const int*   x0     = (const int*)d_in[4];
    const int*   y0     = (const int*)d_in[5];
    const int*   x1     = (const int*)d_in[6];
    const int*   y1     = (const int*)d_in[7];
    const float* W1     = (const float*)d_in[8];
    const float* b1     = (const float*)d_in[9];
    const float* W2     = (const float*)d_in[10];
    const float* b2     = (const float*)d_in[11];
    const float* W3     = (const float*)d_in[12];
    const float* b3     = (const float*)d_in[13];
    float* out = (float*)d_out;

    g_tensor3d_kernel<<<NPIX / 128, 128>>>(z, data, z_data, lerp,
                                           x0, y0, x1, y1,
                                           W1, b1, W2, b2, W3, b3, out);
}